// round 1
// baseline (speedup 1.0000x reference)
#include <cuda_runtime.h>
#include <math.h>

// Problem constants
#define Bsz 640
#define Dd 512
#define Ss 4
#define Tt 10
#define TBsz 64
#define Ll 30
#define KBsz 196
#define MKB (Bsz*KBsz)   // 125440
#define TS 40            // T*S

// ---------------- scratch (static device globals; no allocations) ----------
__device__ float g_q0[Bsz*Dd];
__device__ float g_qall[Ss*Bsz*Dd];          // (s, b, d)
__device__ float g_ch[Bsz*Ss*Dd];            // (b, s, d)
__device__ float g_chkey[Bsz*Ss*Dd];
__device__ float g_chval[Bsz*Ss*Dd];
__device__ float g_normed[Bsz*Ss*Dd];
__device__ float g_Amat[TBsz*TS*TS];
__device__ float g_att[Bsz*Ss*Dd];           // (b, s, d)
__device__ float g_kp [(size_t)MKB*Dd];      // know_proj
__device__ float g_kp2[(size_t)MKB*Dd];      // know_proj @ concat_w[D:] + concat_b
__device__ float g_e1 [(size_t)MKB*Dd];      // elu(inter @ W_top + kp2)
__device__ float g_mp[Bsz*Dd];
__device__ float g_s[MKB];
__device__ float g_read[Bsz*Dd];
__device__ float g_mem0[Bsz*Dd];
__device__ float g_mem1[Bsz*Dd];

__device__ __forceinline__ float eluf(float x){ return x > 0.f ? x : expm1f(x); }

// ---------------- generic tiled SGEMM ---------------------------------------
// C[M,N] = epilogue( A'[M,K] @ W[K,N] )    W row-major with stride N.
// A'[m,k] = (k < splitK ? A[m*lda+k] : A2[m*lda2+k-splitK]),
//           optionally * rowscale[(m/KB)*512 + k]   (MODE 2)
// MODE 0: C = acc + bias
// MODE 1: C = tanh(acc + bias)
// MODE 2: C = elu(acc + addmat[m*N+n])              (bias folded into addmat)
// MODE 3: no C; svec[m] += sum_n elu((acc+bias[n])*colmul[(m/KB)*cmStride+n])*rvec[n]
// Requires: M % 128 == 0, N % 128 == 0, K % 16 == 0.
#define BM 128
#define BN 128
#define BKK 16

template<int MODE>
__global__ __launch_bounds__(256, 2)
void sgemm_k(const float* __restrict__ A, int lda,
             const float* __restrict__ A2, int lda2, int splitK,
             const float* __restrict__ W,
             const float* __restrict__ bias,
             float* __restrict__ C,
             int M, int K, int N,
             const float* __restrict__ rowscale,
             const float* __restrict__ addmat,
             const float* __restrict__ colmul, int cmStride,
             const float* __restrict__ rvec,
             float* __restrict__ svec)
{
    __shared__ float As[BKK][BM];
    __shared__ float Bs[BKK][BN];

    const int bm = blockIdx.y * BM;
    const int bn = blockIdx.x * BN;
    const int tid = threadIdx.x;
    const int ty = tid >> 4;        // 0..15
    const int tx = tid & 15;        // 0..15

    float acc[8][8];
    #pragma unroll
    for (int i = 0; i < 8; i++)
        #pragma unroll
        for (int j = 0; j < 8; j++) acc[i][j] = 0.f;

    for (int k0 = 0; k0 < K; k0 += BKK) {
        // ---- load A tile (128 x 16), 2 float4 per thread, store transposed
        #pragma unroll
        for (int e2 = 0; e2 < 2; e2++) {
            int e   = tid * 2 + e2;          // 0..511
            int row = e >> 2;                // 0..127
            int kq  = (e & 3) * 4;           // 0,4,8,12
            int m   = bm + row;
            int k   = k0 + kq;
            const float* src = (k < splitK)
                ? (A  + (size_t)m * lda  + k)
                : (A2 + (size_t)m * lda2 + (k - splitK));
            float4 v = *(const float4*)src;
            if (MODE == 2) {
                int b = m / KBsz;
                float4 rs = *(const float4*)(rowscale + (size_t)b * Dd + k);
                v.x *= rs.x; v.y *= rs.y; v.z *= rs.z; v.w *= rs.w;
            }
            As[kq + 0][row] = v.x; As[kq + 1][row] = v.y;
            As[kq + 2][row] = v.z; As[kq + 3][row] = v.w;
        }
        // ---- load B tile (16 x 128), 2 float4 per thread
        #pragma unroll
        for (int e2 = 0; e2 < 2; e2++) {
            int e   = tid * 2 + e2;          // 0..511
            int row = e >> 5;                // 0..15
            int c   = (e & 31) * 4;          // 0..124
            float4 v = *(const float4*)(W + (size_t)(k0 + row) * N + bn + c);
            *(float4*)&Bs[row][c] = v;
        }
        __syncthreads();
        #pragma unroll
        for (int kk = 0; kk < BKK; kk++) {
            float a[8], bb[8];
            #pragma unroll
            for (int i = 0; i < 8; i++) a[i]  = As[kk][ty * 8 + i];
            #pragma unroll
            for (int j = 0; j < 8; j++) bb[j] = Bs[kk][tx * 8 + j];
            #pragma unroll
            for (int i = 0; i < 8; i++)
                #pragma unroll
                for (int j = 0; j < 8; j++)
                    acc[i][j] = fmaf(a[i], bb[j], acc[i][j]);
        }
        __syncthreads();
    }

    if (MODE == 3) {
        __shared__ float sred[BM];
        if (tid < BM) sred[tid] = 0.f;
        __syncthreads();
        #pragma unroll
        for (int i = 0; i < 8; i++) {
            int m = bm + ty * 8 + i;
            int b = m / KBsz;
            float part = 0.f;
            #pragma unroll
            for (int j = 0; j < 8; j++) {
                int n = bn + tx * 8 + j;
                float v = acc[i][j] + bias[n];
                v *= colmul[(size_t)b * cmStride + n];
                v = eluf(v);
                part += v * rvec[n];
            }
            atomicAdd(&sred[ty * 8 + i], part);
        }
        __syncthreads();
        if (tid < BM) atomicAdd(&svec[bm + tid], sred[tid]);
        return;
    }

    #pragma unroll
    for (int i = 0; i < 8; i++) {
        int m = bm + ty * 8 + i;
        #pragma unroll
        for (int j = 0; j < 8; j += 4) {
            int n = bn + tx * 8 + j;
            float4 v;
            v.x = acc[i][j]; v.y = acc[i][j+1]; v.z = acc[i][j+2]; v.w = acc[i][j+3];
            if (MODE == 2) {
                float4 ad = *(const float4*)(addmat + (size_t)m * N + n);
                v.x = eluf(v.x + ad.x); v.y = eluf(v.y + ad.y);
                v.z = eluf(v.z + ad.z); v.w = eluf(v.w + ad.w);
            } else {
                v.x += bias[n]; v.y += bias[n+1]; v.z += bias[n+2]; v.w += bias[n+3];
                if (MODE == 1) { v.x = tanhf(v.x); v.y = tanhf(v.y); v.z = tanhf(v.z); v.w = tanhf(v.w); }
            }
            *(float4*)(C + (size_t)m * N + n) = v;
        }
    }
}

// ---------------- step C: per-(b,s) word attention ---------------------------
__global__ void word_attn_k(const float* __restrict__ qall,
                            const float* __restrict__ qword,
                            const float* __restrict__ caw,
                            float* __restrict__ ch)
{
    int b = blockIdx.x, s = blockIdx.y;
    __shared__ float qs[Dd];
    __shared__ float lg[Ll];
    int tid = threadIdx.x;
    for (int d = tid; d < Dd; d += 256)
        qs[d] = qall[((size_t)s * Bsz + b) * Dd + d] * caw[d];
    __syncthreads();
    int wid = tid >> 5, lane = tid & 31;
    for (int l = wid; l < Ll; l += 8) {
        const float* qw = qword + ((size_t)b * Ll + l) * Dd;
        float a = 0.f;
        for (int d = lane; d < Dd; d += 32) a += qs[d] * qw[d];
        #pragma unroll
        for (int o = 16; o; o >>= 1) a += __shfl_xor_sync(0xffffffffu, a, o);
        if (lane == 0) lg[l] = a;
    }
    __syncthreads();
    if (tid == 0) {
        float mx = -INFINITY;
        for (int l = 0; l < Ll; l++) mx = fmaxf(mx, lg[l]);
        float sm = 0.f;
        for (int l = 0; l < Ll; l++) { float e = expf(lg[l] - mx); lg[l] = e; sm += e; }
        float inv = 1.f / sm;
        for (int l = 0; l < Ll; l++) lg[l] *= inv;
    }
    __syncthreads();
    for (int d = tid; d < Dd; d += 256) {
        float a = 0.f;
        for (int l = 0; l < Ll; l++) a += lg[l] * qword[((size_t)b * Ll + l) * Dd + d];
        ch[((size_t)b * Ss + s) * Dd + d] = a;
    }
}

// ---------------- norm over S axis -------------------------------------------
__global__ void norm_k(const float* __restrict__ chkey, float* __restrict__ normed)
{
    int i = blockIdx.x * blockDim.x + threadIdx.x;
    if (i >= Bsz * Dd) return;
    int b = i >> 9, d = i & 511;
    size_t base = (size_t)b * Ss * Dd + d;
    float ss = 0.f;
    #pragma unroll
    for (int s = 0; s < Ss; s++) { float v = chkey[base + s * Dd]; ss += v * v; }
    float inv = 1.f / sqrtf(ss);
    #pragma unroll
    for (int s = 0; s < Ss; s++) normed[base + s * Dd] = chkey[base + s * Dd] * inv;
}

// ---------------- causal self-attn over the 40-step sequence -----------------
__global__ void gram_k(const float* __restrict__ normed, float* __restrict__ Amat)
{
    int tb = blockIdx.x, i = blockIdx.y;
    __shared__ float Ki[Dd];
    __shared__ float lg[TS];
    int tid = threadIdx.x;
    int ti = i / Ss, si = i % Ss;
    size_t rowi = ((size_t)(ti * TBsz + tb) * Ss + si) * Dd;
    for (int d = tid; d < Dd; d += 256) Ki[d] = normed[rowi + d];
    __syncthreads();
    int wid = tid >> 5, lane = tid & 31;
    for (int j = wid; j < TS; j += 8) {
        float a;
        if (j > i) a = -1e30f;
        else {
            int tj = j / Ss, sj = j % Ss;
            size_t rowj = ((size_t)(tj * TBsz + tb) * Ss + sj) * Dd;
            a = 0.f;
            for (int d = lane; d < Dd; d += 32) a += Ki[d] * normed[rowj + d];
            #pragma unroll
            for (int o = 16; o; o >>= 1) a += __shfl_xor_sync(0xffffffffu, a, o);
        }
        if (lane == 0) lg[j] = a;
    }
    __syncthreads();
    if (tid == 0) {
        float mx = -INFINITY;
        for (int j = 0; j < TS; j++) mx = fmaxf(mx, lg[j]);
        float sm = 0.f;
        for (int j = 0; j < TS; j++) { float e = expf(lg[j] - mx); lg[j] = e; sm += e; }
        float inv = 1.f / sm;
        for (int j = 0; j < TS; j++) lg[j] *= inv;
    }
    __syncthreads();
    if (tid < TS) Amat[((size_t)tb * TS + i) * TS + tid] = lg[tid];
}

__global__ void attv_k(const float* __restrict__ Amat,
                       const float* __restrict__ chval,
                       float* __restrict__ att)
{
    int tb = blockIdx.x, i = blockIdx.y;
    __shared__ float aw[TS];
    int tid = threadIdx.x;
    if (tid < TS) aw[tid] = Amat[((size_t)tb * TS + i) * TS + tid];
    __syncthreads();
    int ti = i / Ss, si = i % Ss;
    for (int d = tid; d < Dd; d += 256) {
        float a = 0.f;
        for (int j = 0; j <= i; j++) {   // strictly causal: rest are exactly 0
            int tj = j / Ss, sj = j % Ss;
            a += aw[j] * chval[((size_t)(tj * TBsz + tb) * Ss + sj) * Dd + d];
        }
        att[((size_t)(ti * TBsz + tb) * Ss + si) * Dd + d] = a;
    }
}

// ---------------- misc small kernels -----------------------------------------
__global__ void bcast_k(const float* __restrict__ src, float* __restrict__ dst)
{
    int i = blockIdx.x * blockDim.x + threadIdx.x;
    if (i < Bsz * Dd) dst[i] = src[i & 511];
}

__global__ void zero_k(float* __restrict__ p, int n)
{
    int i = blockIdx.x * blockDim.x + threadIdx.x;
    if (i < n) p[i] = 0.f;
}

// per-b softmax over KB scores + weighted read of knowledge
__global__ void read_k(const float* __restrict__ s,
                       const float* __restrict__ knowledge,
                       float* __restrict__ readv)
{
    int b = blockIdx.x;
    __shared__ float sv[KBsz];
    int tid = threadIdx.x;
    if (tid < KBsz) sv[tid] = s[(size_t)b * KBsz + tid];
    __syncthreads();
    if (tid == 0) {
        float mx = -INFINITY;
        for (int k = 0; k < KBsz; k++) mx = fmaxf(mx, sv[k]);
        float sm = 0.f;
        for (int k = 0; k < KBsz; k++) { float e = expf(sv[k] - mx); sv[k] = e; sm += e; }
        float inv = 1.f / sm;
        for (int k = 0; k < KBsz; k++) sv[k] *= inv;
    }
    __syncthreads();
    for (int d = tid; d < Dd; d += 256) {
        float a = 0.f;
        for (int k = 0; k < KBsz; k++)
            a += sv[k] * knowledge[((size_t)b * KBsz + k) * Dd + d];
        readv[(size_t)b * Dd + d] = a;
    }
}

__global__ void out_k(const float* __restrict__ mem,
                      const float* __restrict__ att,
                      float* __restrict__ out, int out_size)
{
    int i = blockIdx.x * blockDim.x + threadIdx.x;
    const int BD = Bsz * Dd;
    if (i >= BD) return;
    if (i < out_size) out[i] = mem[i];
    if (out_size >= 2 * BD) {
        int b = i >> 9, d = i & 511;
        out[BD + i] = att[((size_t)b * Ss + (Ss - 1)) * Dd + d];
    }
}

// ---------------- launch -----------------------------------------------------
static float* sym(const void* s) { void* p = nullptr; cudaGetSymbolAddress(&p, s); return (float*)p; }

extern "C" void kernel_launch(void* const* d_in, const int* in_sizes, int n_in,
                              void* d_out, int out_size)
{
    const float* qword     = (const float*)d_in[0];
    const float* qemb      = (const float*)d_in[1];
    const float* knowledge = (const float*)d_in[2];
    // d_in[3] = question_lengths (unused by the reference)
    const float* ci_w     = (const float*)d_in[4];
    const float* ci_b     = (const float*)d_in[5];
    const float* ciu_w    = (const float*)d_in[6];
    const float* ciu_b    = (const float*)d_in[7];
    const float* ca_w     = (const float*)d_in[8];
    const float* kproj_w  = (const float*)d_in[10];
    const float* kproj_b  = (const float*)d_in[11];
    const float* mproj_w  = (const float*)d_in[12];
    const float* mproj_b  = (const float*)d_in[13];
    const float* concat_w = (const float*)d_in[14];
    const float* concat_b = (const float*)d_in[15];
    const float* concat2_w= (const float*)d_in[16];
    const float* concat2_b= (const float*)d_in[17];
    const float* rattn_w  = (const float*)d_in[18];
    const float* write_w  = (const float*)d_in[20];
    const float* write_b  = (const float*)d_in[21];
    const float* init_mem = (const float*)d_in[22];
    const float* kq_w     = (const float*)d_in[23];
    const float* kq_b     = (const float*)d_in[24];
    const float* val_w    = (const float*)d_in[25];
    const float* val_b    = (const float*)d_in[26];
    float* out = (float*)d_out;

    float* q0    = sym(g_q0);
    float* qall  = sym(g_qall);
    float* ch    = sym(g_ch);
    float* chkey = sym(g_chkey);
    float* chval = sym(g_chval);
    float* normed= sym(g_normed);
    float* Amat  = sym(g_Amat);
    float* att   = sym(g_att);
    float* kp    = sym(g_kp);
    float* kp2   = sym(g_kp2);
    float* e1    = sym(g_e1);
    float* mp    = sym(g_mp);
    float* sbuf  = sym(g_s);
    float* readv = sym(g_read);
    float* mem0  = sym(g_mem0);
    float* mem1  = sym(g_mem1);

    auto G = [](int M, int N) { return dim3(N / BN, M / BM); };
    const float* NPF = nullptr;

    // q0 = tanh(qemb @ ci_w + ci_b)
    sgemm_k<1><<<G(Bsz, Dd), 256>>>(qemb, Dd, qemb, Dd, Dd, ci_w, ci_b, q0,
                                    Bsz, Dd, Dd, NPF, NPF, NPF, 0, NPF, nullptr);
    // qall[s] = q0 @ ciu_w[s] + ciu_b[s]
    for (int s = 0; s < Ss; s++)
        sgemm_k<0><<<G(Bsz, Dd), 256>>>(q0, Dd, q0, Dd, Dd,
                                        ciu_w + (size_t)s * Dd * Dd, ciu_b + s * Dd,
                                        qall + (size_t)s * Bsz * Dd,
                                        Bsz, Dd, Dd, NPF, NPF, NPF, 0, NPF, nullptr);
    // word attention -> ch
    word_attn_k<<<dim3(Bsz, Ss), 256>>>(qall, qword, ca_w, ch);
    // ch_key / ch_val
    sgemm_k<0><<<G(Bsz * Ss, Dd), 256>>>(ch, Dd, ch, Dd, Dd, kq_w, kq_b, chkey,
                                         Bsz * Ss, Dd, Dd, NPF, NPF, NPF, 0, NPF, nullptr);
    sgemm_k<0><<<G(Bsz * Ss, Dd), 256>>>(ch, Dd, ch, Dd, Dd, val_w, val_b, chval,
                                         Bsz * Ss, Dd, Dd, NPF, NPF, NPF, 0, NPF, nullptr);
    // norm over S, causal self-attn, att
    norm_k<<<(Bsz * Dd + 255) / 256, 256>>>(chkey, normed);
    gram_k<<<dim3(TBsz, TS), 256>>>(normed, Amat);
    attv_k<<<dim3(TBsz, TS), 256>>>(Amat, chval, att);
    // know_proj, kp2 (loop-invariant)
    sgemm_k<0><<<G(MKB, Dd), 256>>>(knowledge, Dd, knowledge, Dd, Dd, kproj_w, kproj_b, kp,
                                    MKB, Dd, Dd, NPF, NPF, NPF, 0, NPF, nullptr);
    sgemm_k<0><<<G(MKB, Dd), 256>>>(kp, Dd, kp, Dd, Dd,
                                    concat_w + (size_t)Dd * Dd, concat_b, kp2,
                                    MKB, Dd, Dd, NPF, NPF, NPF, 0, NPF, nullptr);
    // memory init
    bcast_k<<<(Bsz * Dd + 255) / 256, 256>>>(init_mem, mem0);

    float* mcur = mem0;
    float* mnext = mem1;
    for (int i = 0; i < Ss; i++) {
        // mp = memory @ mproj_w + mproj_b
        sgemm_k<0><<<G(Bsz, Dd), 256>>>(mcur, Dd, mcur, Dd, Dd, mproj_w, mproj_b, mp,
                                        Bsz, Dd, Dd, NPF, NPF, NPF, 0, NPF, nullptr);
        // E1 = elu((kp * mp[b]) @ concat_w_top + kp2)
        sgemm_k<2><<<G(MKB, Dd), 256>>>(kp, Dd, kp, Dd, Dd, concat_w, NPF, e1,
                                        MKB, Dd, Dd, mp, kp2, NPF, 0, NPF, nullptr);
        // scores: s[m] = sum_n elu((E1@concat2_w + b)*control)*rattn_w
        zero_k<<<(MKB + 255) / 256, 256>>>(sbuf, MKB);
        sgemm_k<3><<<G(MKB, Dd), 256>>>(e1, Dd, e1, Dd, Dd, concat2_w, concat2_b, nullptr,
                                        MKB, Dd, Dd, NPF, NPF,
                                        att + (size_t)i * Dd, Ss * Dd, rattn_w, sbuf);
        // softmax over KB + weighted read of knowledge
        read_k<<<Bsz, 256>>>(sbuf, knowledge, readv);
        // memory' = [memory, read] @ write_w + write_b
        sgemm_k<0><<<G(Bsz, Dd), 256>>>(mcur, Dd, readv, Dd, Dd, write_w, write_b, mnext,
                                        Bsz, 2 * Dd, Dd, NPF, NPF, NPF, 0, NPF, nullptr);
        float* t = mcur; mcur = mnext; mnext = t;
    }

    out_k<<<(Bsz * Dd + 255) / 256, 256>>>(mcur, att, out, out_size);
}

// round 2
// speedup vs baseline: 1.0504x; 1.0504x over previous
#include <cuda_runtime.h>
#include <math.h>

// Problem constants
#define Bsz 640
#define Dd 512
#define Ss 4
#define Tt 10
#define TBsz 64
#define Ll 30
#define KBsz 196
#define MKB (Bsz*KBsz)   // 125440
#define TS 40            // T*S

// ---------------- scratch (static device globals; no allocations) ----------
__device__ float g_q0[Bsz*Dd];
__device__ float g_qall[Ss*Bsz*Dd];          // (s, b, d)
__device__ float g_ch[Bsz*Ss*Dd];            // (b, s, d)
__device__ float g_chkey[Bsz*Ss*Dd];
__device__ float g_chval[Bsz*Ss*Dd];
__device__ float g_normed[Bsz*Ss*Dd];
__device__ float g_Amat[TBsz*TS*TS];
__device__ float g_att[Bsz*Ss*Dd];           // (b, s, d)
__device__ float g_kp [(size_t)MKB*Dd];      // know_proj
__device__ float g_kp2[(size_t)MKB*Dd];      // know_proj @ concat_w[D:] + concat_b
__device__ float g_e1 [(size_t)MKB*Dd];      // elu(inter @ W_top + kp2)
__device__ float g_mp[Bsz*Dd];
__device__ float g_s[MKB];
__device__ float g_read[Bsz*Dd];
__device__ float g_mem0[Bsz*Dd];
__device__ float g_mem1[Bsz*Dd];

__device__ __forceinline__ float eluf(float x){ return x > 0.f ? x : expm1f(x); }

// packed f32x2 helpers (FFMA2 path — ptxas only emits it from this PTX form)
__device__ __forceinline__ unsigned long long pack2(float lo, float hi) {
    unsigned long long r;
    asm("mov.b64 %0, {%1, %2};" : "=l"(r) : "f"(lo), "f"(hi));
    return r;
}
__device__ __forceinline__ void unpack2(unsigned long long v, float& lo, float& hi) {
    asm("mov.b64 {%0, %1}, %2;" : "=f"(lo), "=f"(hi) : "l"(v));
}
__device__ __forceinline__ void fma2(unsigned long long& d,
                                     unsigned long long a, unsigned long long b) {
    asm("fma.rn.f32x2 %0, %1, %2, %0;" : "+l"(d) : "l"(a), "l"(b));
}

// ---------------- generic tiled SGEMM (FFMA2 mainloop) -----------------------
// C[M,N] = epilogue( A'[M,K] @ W[K,N] )    W row-major with stride N.
// A'[m,k] = (k < splitK ? A[m*lda+k] : A2[m*lda2+k-splitK]),
//           optionally * rowscale[(m/KB)*512 + k]   (MODE 2)
// MODE 0: C = acc + bias
// MODE 1: C = tanh(acc + bias)
// MODE 2: C = elu(acc + addmat[m*N+n])              (bias folded into addmat)
// MODE 3: no C; svec[m] += sum_n elu((acc+bias[n])*colmul[(m/KB)*cmStride+n])*rvec[n]
// Requires: M % 128 == 0, N % 128 == 0, K % 16 == 0.
#define BM 128
#define BN 128
#define BKK 16

template<int MODE>
__global__ __launch_bounds__(256, 2)
void sgemm_k(const float* __restrict__ A, int lda,
             const float* __restrict__ A2, int lda2, int splitK,
             const float* __restrict__ W,
             const float* __restrict__ bias,
             float* __restrict__ C,
             int M, int K, int N,
             const float* __restrict__ rowscale,
             const float* __restrict__ addmat,
             const float* __restrict__ colmul, int cmStride,
             const float* __restrict__ rvec,
             float* __restrict__ svec)
{
    __shared__ float As[BKK][BM];
    __shared__ float Bs[BKK][BN];

    const int bm = blockIdx.y * BM;
    const int bn = blockIdx.x * BN;
    const int tid = threadIdx.x;
    const int ty = tid >> 4;        // 0..15
    const int tx = tid & 15;        // 0..15

    // 8x8 microtile as 8x4 packed f32x2 pairs along j
    unsigned long long acc2[8][4];
    #pragma unroll
    for (int i = 0; i < 8; i++)
        #pragma unroll
        for (int j = 0; j < 4; j++) acc2[i][j] = 0ull;

    for (int k0 = 0; k0 < K; k0 += BKK) {
        // ---- load A tile (128 x 16), 2 float4 per thread, store transposed
        #pragma unroll
        for (int e2 = 0; e2 < 2; e2++) {
            int e   = tid * 2 + e2;          // 0..511
            int row = e >> 2;                // 0..127
            int kq  = (e & 3) * 4;           // 0,4,8,12
            int m   = bm + row;
            int k   = k0 + kq;
            const float* src = (k < splitK)
                ? (A  + (size_t)m * lda  + k)
                : (A2 + (size_t)m * lda2 + (k - splitK));
            float4 v = *(const float4*)src;
            if (MODE == 2) {
                int b = m / KBsz;
                float4 rs = *(const float4*)(rowscale + (size_t)b * Dd + k);
                v.x *= rs.x; v.y *= rs.y; v.z *= rs.z; v.w *= rs.w;
            }
            As[kq + 0][row] = v.x; As[kq + 1][row] = v.y;
            As[kq + 2][row] = v.z; As[kq + 3][row] = v.w;
        }
        // ---- load B tile (16 x 128), 2 float4 per thread
        #pragma unroll
        for (int e2 = 0; e2 < 2; e2++) {
            int e   = tid * 2 + e2;          // 0..511
            int row = e >> 5;                // 0..15
            int c   = (e & 31) * 4;          // 0..124
            float4 v = *(const float4*)(W + (size_t)(k0 + row) * N + bn + c);
            *(float4*)&Bs[row][c] = v;
        }
        __syncthreads();
        #pragma unroll
        for (int kk = 0; kk < BKK; kk++) {
            float a[8];
            unsigned long long b2[4];
            #pragma unroll
            for (int i = 0; i < 8; i++) a[i] = As[kk][ty * 8 + i];
            #pragma unroll
            for (int j = 0; j < 4; j++)
                b2[j] = *(const unsigned long long*)&Bs[kk][tx * 8 + j * 2];
            #pragma unroll
            for (int i = 0; i < 8; i++) {
                unsigned long long pa = pack2(a[i], a[i]);   // alu pipe, overlaps fma
                #pragma unroll
                for (int j = 0; j < 4; j++)
                    fma2(acc2[i][j], pa, b2[j]);             // FFMA2
            }
        }
        __syncthreads();
    }

    // unpack accumulators
    float acc[8][8];
    #pragma unroll
    for (int i = 0; i < 8; i++)
        #pragma unroll
        for (int j = 0; j < 4; j++)
            unpack2(acc2[i][j], acc[i][2 * j], acc[i][2 * j + 1]);

    if (MODE == 3) {
        __shared__ float sred[BM];
        if (tid < BM) sred[tid] = 0.f;
        __syncthreads();
        #pragma unroll
        for (int i = 0; i < 8; i++) {
            int m = bm + ty * 8 + i;
            int b = m / KBsz;
            float part = 0.f;
            #pragma unroll
            for (int j = 0; j < 8; j++) {
                int n = bn + tx * 8 + j;
                float v = acc[i][j] + bias[n];
                v *= colmul[(size_t)b * cmStride + n];
                v = eluf(v);
                part += v * rvec[n];
            }
            atomicAdd(&sred[ty * 8 + i], part);
        }
        __syncthreads();
        if (tid < BM) atomicAdd(&svec[bm + tid], sred[tid]);
        return;
    }

    #pragma unroll
    for (int i = 0; i < 8; i++) {
        int m = bm + ty * 8 + i;
        #pragma unroll
        for (int j = 0; j < 8; j += 4) {
            int n = bn + tx * 8 + j;
            float4 v;
            v.x = acc[i][j]; v.y = acc[i][j+1]; v.z = acc[i][j+2]; v.w = acc[i][j+3];
            if (MODE == 2) {
                float4 ad = *(const float4*)(addmat + (size_t)m * N + n);
                v.x = eluf(v.x + ad.x); v.y = eluf(v.y + ad.y);
                v.z = eluf(v.z + ad.z); v.w = eluf(v.w + ad.w);
            } else {
                v.x += bias[n]; v.y += bias[n+1]; v.z += bias[n+2]; v.w += bias[n+3];
                if (MODE == 1) { v.x = tanhf(v.x); v.y = tanhf(v.y); v.z = tanhf(v.z); v.w = tanhf(v.w); }
            }
            *(float4*)(C + (size_t)m * N + n) = v;
        }
    }
}

// ---------------- step C: per-(b,s) word attention ---------------------------
__global__ void word_attn_k(const float* __restrict__ qall,
                            const float* __restrict__ qword,
                            const float* __restrict__ caw,
                            float* __restrict__ ch)
{
    int b = blockIdx.x, s = blockIdx.y;
    __shared__ float qs[Dd];
    __shared__ float lg[Ll];
    int tid = threadIdx.x;
    for (int d = tid; d < Dd; d += 256)
        qs[d] = qall[((size_t)s * Bsz + b) * Dd + d] * caw[d];
    __syncthreads();
    int wid = tid >> 5, lane = tid & 31;
    for (int l = wid; l < Ll; l += 8) {
        const float* qw = qword + ((size_t)b * Ll + l) * Dd;
        float a = 0.f;
        for (int d = lane; d < Dd; d += 32) a += qs[d] * qw[d];
        #pragma unroll
        for (int o = 16; o; o >>= 1) a += __shfl_xor_sync(0xffffffffu, a, o);
        if (lane == 0) lg[l] = a;
    }
    __syncthreads();
    if (tid == 0) {
        float mx = -INFINITY;
        for (int l = 0; l < Ll; l++) mx = fmaxf(mx, lg[l]);
        float sm = 0.f;
        for (int l = 0; l < Ll; l++) { float e = expf(lg[l] - mx); lg[l] = e; sm += e; }
        float inv = 1.f / sm;
        for (int l = 0; l < Ll; l++) lg[l] *= inv;
    }
    __syncthreads();
    for (int d = tid; d < Dd; d += 256) {
        float a = 0.f;
        for (int l = 0; l < Ll; l++) a += lg[l] * qword[((size_t)b * Ll + l) * Dd + d];
        ch[((size_t)b * Ss + s) * Dd + d] = a;
    }
}

// ---------------- norm over S axis -------------------------------------------
__global__ void norm_k(const float* __restrict__ chkey, float* __restrict__ normed)
{
    int i = blockIdx.x * blockDim.x + threadIdx.x;
    if (i >= Bsz * Dd) return;
    int b = i >> 9, d = i & 511;
    size_t base = (size_t)b * Ss * Dd + d;
    float ss = 0.f;
    #pragma unroll
    for (int s = 0; s < Ss; s++) { float v = chkey[base + s * Dd]; ss += v * v; }
    float inv = 1.f / sqrtf(ss);
    #pragma unroll
    for (int s = 0; s < Ss; s++) normed[base + s * Dd] = chkey[base + s * Dd] * inv;
}

// ---------------- causal self-attn over the 40-step sequence -----------------
__global__ void gram_k(const float* __restrict__ normed, float* __restrict__ Amat)
{
    int tb = blockIdx.x, i = blockIdx.y;
    __shared__ float Ki[Dd];
    __shared__ float lg[TS];
    int tid = threadIdx.x;
    int ti = i / Ss, si = i % Ss;
    size_t rowi = ((size_t)(ti * TBsz + tb) * Ss + si) * Dd;
    for (int d = tid; d < Dd; d += 256) Ki[d] = normed[rowi + d];
    __syncthreads();
    int wid = tid >> 5, lane = tid & 31;
    for (int j = wid; j < TS; j += 8) {
        float a;
        if (j > i) a = -1e30f;
        else {
            int tj = j / Ss, sj = j % Ss;
            size_t rowj = ((size_t)(tj * TBsz + tb) * Ss + sj) * Dd;
            a = 0.f;
            for (int d = lane; d < Dd; d += 32) a += Ki[d] * normed[rowj + d];
            #pragma unroll
            for (int o = 16; o; o >>= 1) a += __shfl_xor_sync(0xffffffffu, a, o);
        }
        if (lane == 0) lg[j] = a;
    }
    __syncthreads();
    if (tid == 0) {
        float mx = -INFINITY;
        for (int j = 0; j < TS; j++) mx = fmaxf(mx, lg[j]);
        float sm = 0.f;
        for (int j = 0; j < TS; j++) { float e = expf(lg[j] - mx); lg[j] = e; sm += e; }
        float inv = 1.f / sm;
        for (int j = 0; j < TS; j++) lg[j] *= inv;
    }
    __syncthreads();
    if (tid < TS) Amat[((size_t)tb * TS + i) * TS + tid] = lg[tid];
}

__global__ void attv_k(const float* __restrict__ Amat,
                       const float* __restrict__ chval,
                       float* __restrict__ att)
{
    int tb = blockIdx.x, i = blockIdx.y;
    __shared__ float aw[TS];
    int tid = threadIdx.x;
    if (tid < TS) aw[tid] = Amat[((size_t)tb * TS + i) * TS + tid];
    __syncthreads();
    int ti = i / Ss, si = i % Ss;
    for (int d = tid; d < Dd; d += 256) {
        float a = 0.f;
        for (int j = 0; j <= i; j++) {   // strictly causal: rest are exactly 0
            int tj = j / Ss, sj = j % Ss;
            a += aw[j] * chval[((size_t)(tj * TBsz + tb) * Ss + sj) * Dd + d];
        }
        att[((size_t)(ti * TBsz + tb) * Ss + si) * Dd + d] = a;
    }
}

// ---------------- misc small kernels -----------------------------------------
__global__ void bcast_k(const float* __restrict__ src, float* __restrict__ dst)
{
    int i = blockIdx.x * blockDim.x + threadIdx.x;
    if (i < Bsz * Dd) dst[i] = src[i & 511];
}

__global__ void zero_k(float* __restrict__ p, int n)
{
    int i = blockIdx.x * blockDim.x + threadIdx.x;
    if (i < n) p[i] = 0.f;
}

// per-b softmax over KB scores + weighted read of knowledge
__global__ void read_k(const float* __restrict__ s,
                       const float* __restrict__ knowledge,
                       float* __restrict__ readv)
{
    int b = blockIdx.x;
    __shared__ float sv[KBsz];
    int tid = threadIdx.x;
    if (tid < KBsz) sv[tid] = s[(size_t)b * KBsz + tid];
    __syncthreads();
    if (tid == 0) {
        float mx = -INFINITY;
        for (int k = 0; k < KBsz; k++) mx = fmaxf(mx, sv[k]);
        float sm = 0.f;
        for (int k = 0; k < KBsz; k++) { float e = expf(sv[k] - mx); sv[k] = e; sm += e; }
        float inv = 1.f / sm;
        for (int k = 0; k < KBsz; k++) sv[k] *= inv;
    }
    __syncthreads();
    for (int d = tid; d < Dd; d += 256) {
        float a = 0.f;
        for (int k = 0; k < KBsz; k++)
            a += sv[k] * knowledge[((size_t)b * KBsz + k) * Dd + d];
        readv[(size_t)b * Dd + d] = a;
    }
}

__global__ void out_k(const float* __restrict__ mem,
                      const float* __restrict__ att,
                      float* __restrict__ out, int out_size)
{
    int i = blockIdx.x * blockDim.x + threadIdx.x;
    const int BD = Bsz * Dd;
    if (i >= BD) return;
    if (i < out_size) out[i] = mem[i];
    if (out_size >= 2 * BD) {
        int b = i >> 9, d = i & 511;
        out[BD + i] = att[((size_t)b * Ss + (Ss - 1)) * Dd + d];
    }
}

// ---------------- launch -----------------------------------------------------
static float* sym(const void* s) { void* p = nullptr; cudaGetSymbolAddress(&p, s); return (float*)p; }

extern "C" void kernel_launch(void* const* d_in, const int* in_sizes, int n_in,
                              void* d_out, int out_size)
{
    const float* qword     = (const float*)d_in[0];
    const float* qemb      = (const float*)d_in[1];
    const float* knowledge = (const float*)d_in[2];
    // d_in[3] = question_lengths (unused by the reference)
    const float* ci_w     = (const float*)d_in[4];
    const float* ci_b     = (const float*)d_in[5];
    const float* ciu_w    = (const float*)d_in[6];
    const float* ciu_b    = (const float*)d_in[7];
    const float* ca_w     = (const float*)d_in[8];
    const float* kproj_w  = (const float*)d_in[10];
    const float* kproj_b  = (const float*)d_in[11];
    const float* mproj_w  = (const float*)d_in[12];
    const float* mproj_b  = (const float*)d_in[13];
    const float* concat_w = (const float*)d_in[14];
    const float* concat_b = (const float*)d_in[15];
    const float* concat2_w= (const float*)d_in[16];
    const float* concat2_b= (const float*)d_in[17];
    const float* rattn_w  = (const float*)d_in[18];
    const float* write_w  = (const float*)d_in[20];
    const float* write_b  = (const float*)d_in[21];
    const float* init_mem = (const float*)d_in[22];
    const float* kq_w     = (const float*)d_in[23];
    const float* kq_b     = (const float*)d_in[24];
    const float* val_w    = (const float*)d_in[25];
    const float* val_b    = (const float*)d_in[26];
    float* out = (float*)d_out;

    float* q0    = sym(g_q0);
    float* qall  = sym(g_qall);
    float* ch    = sym(g_ch);
    float* chkey = sym(g_chkey);
    float* chval = sym(g_chval);
    float* normed= sym(g_normed);
    float* Amat  = sym(g_Amat);
    float* att   = sym(g_att);
    float* kp    = sym(g_kp);
    float* kp2   = sym(g_kp2);
    float* e1    = sym(g_e1);
    float* mp    = sym(g_mp);
    float* sbuf  = sym(g_s);
    float* readv = sym(g_read);
    float* mem0  = sym(g_mem0);
    float* mem1  = sym(g_mem1);

    auto G = [](int M, int N) { return dim3(N / BN, M / BM); };
    const float* NPF = nullptr;

    // q0 = tanh(qemb @ ci_w + ci_b)
    sgemm_k<1><<<G(Bsz, Dd), 256>>>(qemb, Dd, qemb, Dd, Dd, ci_w, ci_b, q0,
                                    Bsz, Dd, Dd, NPF, NPF, NPF, 0, NPF, nullptr);
    // qall[s] = q0 @ ciu_w[s] + ciu_b[s]
    for (int s = 0; s < Ss; s++)
        sgemm_k<0><<<G(Bsz, Dd), 256>>>(q0, Dd, q0, Dd, Dd,
                                        ciu_w + (size_t)s * Dd * Dd, ciu_b + s * Dd,
                                        qall + (size_t)s * Bsz * Dd,
                                        Bsz, Dd, Dd, NPF, NPF, NPF, 0, NPF, nullptr);
    // word attention -> ch
    word_attn_k<<<dim3(Bsz, Ss), 256>>>(qall, qword, ca_w, ch);
    // ch_key / ch_val
    sgemm_k<0><<<G(Bsz * Ss, Dd), 256>>>(ch, Dd, ch, Dd, Dd, kq_w, kq_b, chkey,
                                         Bsz * Ss, Dd, Dd, NPF, NPF, NPF, 0, NPF, nullptr);
    sgemm_k<0><<<G(Bsz * Ss, Dd), 256>>>(ch, Dd, ch, Dd, Dd, val_w, val_b, chval,
                                         Bsz * Ss, Dd, Dd, NPF, NPF, NPF, 0, NPF, nullptr);
    // norm over S, causal self-attn, att
    norm_k<<<(Bsz * Dd + 255) / 256, 256>>>(chkey, normed);
    gram_k<<<dim3(TBsz, TS), 256>>>(normed, Amat);
    attv_k<<<dim3(TBsz, TS), 256>>>(Amat, chval, att);
    // know_proj, kp2 (loop-invariant)
    sgemm_k<0><<<G(MKB, Dd), 256>>>(knowledge, Dd, knowledge, Dd, Dd, kproj_w, kproj_b, kp,
                                    MKB, Dd, Dd, NPF, NPF, NPF, 0, NPF, nullptr);
    sgemm_k<0><<<G(MKB, Dd), 256>>>(kp, Dd, kp, Dd, Dd,
                                    concat_w + (size_t)Dd * Dd, concat_b, kp2,
                                    MKB, Dd, Dd, NPF, NPF, NPF, 0, NPF, nullptr);
    // memory init
    bcast_k<<<(Bsz * Dd + 255) / 256, 256>>>(init_mem, mem0);

    float* mcur = mem0;
    float* mnext = mem1;
    for (int i = 0; i < Ss; i++) {
        // mp = memory @ mproj_w + mproj_b
        sgemm_k<0><<<G(Bsz, Dd), 256>>>(mcur, Dd, mcur, Dd, Dd, mproj_w, mproj_b, mp,
                                        Bsz, Dd, Dd, NPF, NPF, NPF, 0, NPF, nullptr);
        // E1 = elu((kp * mp[b]) @ concat_w_top + kp2)
        sgemm_k<2><<<G(MKB, Dd), 256>>>(kp, Dd, kp, Dd, Dd, concat_w, NPF, e1,
                                        MKB, Dd, Dd, mp, kp2, NPF, 0, NPF, nullptr);
        // scores: s[m] = sum_n elu((E1@concat2_w + b)*control)*rattn_w
        zero_k<<<(MKB + 255) / 256, 256>>>(sbuf, MKB);
        sgemm_k<3><<<G(MKB, Dd), 256>>>(e1, Dd, e1, Dd, Dd, concat2_w, concat2_b, nullptr,
                                        MKB, Dd, Dd, NPF, NPF,
                                        att + (size_t)i * Dd, Ss * Dd, rattn_w, sbuf);
        // softmax over KB + weighted read of knowledge
        read_k<<<Bsz, 256>>>(sbuf, knowledge, readv);
        // memory' = [memory, read] @ write_w + write_b
        sgemm_k<0><<<G(Bsz, Dd), 256>>>(mcur, Dd, readv, Dd, Dd, write_w, write_b, mnext,
                                        Bsz, 2 * Dd, Dd, NPF, NPF, NPF, 0, NPF, nullptr);
        float* t = mcur; mcur = mnext; mnext = t;
    }

    out_k<<<(Bsz * Dd + 255) / 256, 256>>>(mcur, att, out, out_size);
}